// round 8
// baseline (speedup 1.0000x reference)
#include <cuda_runtime.h>
#include <cstdint>
#include <cstddef>

// Problem constants
#define B_      512
#define L_      512
#define KOBS    103
#define H_      512
#define G4      2048          // 4*H
#define KXY     108           // x(103) + y(2) + pad(3)
#define KW      620           // total packed K (108 + 512)
#define NKB     (KW/4)        // 155 k-chunks
#define MB      32            // batch rows per cluster group
#define NPAIR   16            // MB/2 row-pairs
#define KROW    624           // inpP row stride in float2 (32B-aligned rows)
#define NTH     1024
#define NCTAS   128           // 16 groups x 8-CTA clusters
#define CLU     8

// Device-global scratch (allocation-free rule: __device__ globals)
__device__ float4 g_Wq[NKB + 1][G4];   // k-major packed weights (+1 guard row)
__device__ float  g_bsum[G4];
__device__ float  g_W1t[H_][64];       // W1 transposed [k][o]
__device__ float  g_W2t[64][16];       // W2 transposed [k][o]
__device__ float  g_hbuf[B_ * H_];     // recurrent h (L2-coherent via cg)
__device__ float  g_ybuf[B_ * 2];      // fed-back predicted pos

// ---------------------------------------------------------------------------
// helpers
// ---------------------------------------------------------------------------
__device__ __forceinline__ unsigned long long pk2(float lo, float hi) {
    unsigned long long r;
    asm("mov.b64 %0, {%1, %2};" : "=l"(r) : "f"(lo), "f"(hi));
    return r;
}
__device__ __forceinline__ void upk2(unsigned long long v, float& lo, float& hi) {
    asm("mov.b64 {%0, %1}, %2;" : "=f"(lo), "=f"(hi) : "l"(v));
}
#define FMA2(acc, a, b) asm("fma.rn.f32x2 %0, %1, %2, %0;" : "+l"(acc) : "l"(a), "l"(b))

__device__ __forceinline__ void cluster_sync_() {
    asm volatile("barrier.cluster.arrive.aligned;" ::: "memory");
    asm volatile("barrier.cluster.wait.aligned;" ::: "memory");
}
__device__ __forceinline__ float sigf(float v)   { return 1.f / (1.f + __expf(-v)); }
__device__ __forceinline__ float tanhf_(float v) { return 2.f / (1.f + __expf(-2.f * v)) - 1.f; }

// ---------------------------------------------------------------------------
// one-time packing: Wq[kb][rho] (k-major), bias fold, W1/W2 transpose.
// rho = rnk*256 + c;  c -> gate q = c>>6, unit j = c&63; gcol = q*H + rnk*64 + j
// k' map: 0..102 x, 103..104 y (W_ih cols 0..104), 105..107 zero, 108..619 h
// ---------------------------------------------------------------------------
__global__ void pack_kernel(const float* __restrict__ W_ih, const float* __restrict__ W_hh,
                            const float* __restrict__ b_ih, const float* __restrict__ b_hh,
                            const float* __restrict__ W1,   const float* __restrict__ W2) {
    int stride = gridDim.x * blockDim.x;
    int t0 = blockIdx.x * blockDim.x + threadIdx.x;
    for (int idx = t0; idx < NKB * G4; idx += stride) {
        int kb  = idx >> 11;           // /2048
        int rho = idx & 2047;
        int r = rho >> 8, q = (rho >> 6) & 3, j = rho & 63;
        int gcol = q * H_ + r * 64 + j;
        float v[4];
        #pragma unroll
        for (int z = 0; z < 4; z++) {
            int k = kb * 4 + z;
            float w = 0.f;
            if (k < 105)                     w = W_ih[gcol * 105 + k];
            else if (k >= KXY && k < KW)     w = W_hh[gcol * H_ + (k - KXY)];
            v[z] = w;
        }
        g_Wq[kb][rho] = make_float4(v[0], v[1], v[2], v[3]);
    }
    for (int idx = t0; idx < G4; idx += stride) {
        int r = idx >> 8, q = (idx >> 6) & 3, j = idx & 63;
        int gcol = q * H_ + r * 64 + j;
        g_bsum[idx] = b_ih[gcol] + b_hh[gcol];
        g_Wq[NKB][idx] = make_float4(0.f, 0.f, 0.f, 0.f);   // prefetch guard row
    }
    for (int idx = t0; idx < H_ * 64; idx += stride) {
        int k = idx >> 6, o = idx & 63;
        g_W1t[k][o] = W1[o * H_ + k];
    }
    for (int idx = t0; idx < 64 * 16; idx += stride) {
        int k = idx >> 4, o = idx & 15;
        g_W2t[k][o] = W2[o * 64 + k];
    }
}

// ---------------------------------------------------------------------------
// persistent recurrent kernel: 16 groups x 8-CTA clusters, 1024 thr/CTA
// ---------------------------------------------------------------------------
struct __align__(16) SM {
    float2 inpP[NPAIR][KROW];   // [row-pair][k'] full input tile     79.9 KB
    float  g_s[4][64][33];      // gates [gate][unit][row] (+pad)     33.0 KB
    float  c_s[64][33];         // cell state slice                    8.3 KB
    float  hm_s[4][H_];         // staged h rows for MLP               8.2 KB
    float  y1[4][64];
    float  y2[4][16];
};

__global__ void __launch_bounds__(NTH, 1) __cluster_dims__(CLU, 1, 1)
lstm_kernel(const float* __restrict__ x,  const float* __restrict__ pos,
            const float* __restrict__ h0, const float* __restrict__ c0,
            const float* __restrict__ b1, const float* __restrict__ b2,
            const float* __restrict__ W3, const float* __restrict__ b3,
            float* __restrict__ out) {
    extern __shared__ char smraw[];
    SM& sm = *reinterpret_cast<SM*>(smraw);

    const int tid = threadIdx.x;
    const int grp = blockIdx.x >> 3;   // batch group (16)
    const int rnk = blockIdx.x & 7;    // cluster rank = hidden slice
    const int b0  = grp * MB;

    // ---- init state ----
    for (int idx = tid; idx < 64 * MB; idx += NTH) {
        int u = idx & 63, row = idx >> 6;
        int b = b0 + row, ug = rnk * 64 + u;
        sm.c_s[u][row] = c0[b * H_ + ug];
        __stcg(&g_hbuf[b * H_ + ug], h0[b * H_ + ug]);
    }
    if (tid < 8) {
        int rr = tid >> 1, o = tid & 1;
        int b = b0 + rnk * 4 + rr;
        __stcg(&g_ybuf[b * 2 + o], pos[b * L_ * 2 + o]);   // pos[:,0,:]
    }
    __threadfence();
    cluster_sync_();

    // GEMM thread mapping: column c (256 per rank), quarter -> which 4 row-pairs
    const int c    = tid & 255;
    const int quar = tid >> 8;          // 0..3
    const int mpb  = quar * 4;
    const int q    = c >> 6, jj = c & 63;
    const int wrho = rnk * 256 + c;
    const float bias = g_bsum[wrho];

    float b1v = 0.f, b2v = 0.f;
    if (tid < 256) b1v = __ldg(&b1[tid & 63]);
    if (tid < 64)  b2v = __ldg(&b2[tid & 15]);

    for (int t = 0; t < L_; t++) {
        // ---- fill input tile: [x_t | y_prev | pad | h_prev] as row-pairs ----
        for (int idx = tid; idx < NPAIR * KW; idx += NTH) {
            int mp = idx / KW;
            int k  = idx - mp * KW;
            int ba = b0 + 2 * mp;
            float va, vb;
            if (k < KOBS) {
                va = x[(ba * L_ + t) * KOBS + k];
                vb = x[((ba + 1) * L_ + t) * KOBS + k];
            } else if (k < 105) {
                va = __ldcg(&g_ybuf[ba * 2 + (k - KOBS)]);
                vb = __ldcg(&g_ybuf[(ba + 1) * 2 + (k - KOBS)]);
            } else if (k < KXY) {
                va = 0.f; vb = 0.f;
            } else {
                va = __ldcg(&g_hbuf[ba * H_ + (k - KXY)]);
                vb = __ldcg(&g_hbuf[(ba + 1) * H_ + (k - KXY)]);
            }
            sm.inpP[mp][k] = make_float2(va, vb);
        }
        cluster_sync_();   // input tiles ready cluster-wide

        // ---- gate GEMM: 1 column x 4 row-pairs, K = 620, k-major weights ----
        unsigned long long acc[4];
        {
            unsigned long long bb = pk2(bias, bias);
            #pragma unroll
            for (int m = 0; m < 4; m++) acc[m] = bb;
        }
        float4 wv = __ldg(&g_Wq[0][wrho]);
        #pragma unroll 2
        for (int kb = 0; kb < NKB; kb++) {
            float4 wn = __ldg(&g_Wq[kb + 1][wrho]);     // prefetch (guard row zeroed)
            unsigned long long w0 = pk2(wv.x, wv.x), w1 = pk2(wv.y, wv.y);
            unsigned long long w2 = pk2(wv.z, wv.z), w3 = pk2(wv.w, wv.w);
            #pragma unroll
            for (int m = 0; m < 4; m++) {
                const ulonglong2* p =
                    reinterpret_cast<const ulonglong2*>(&sm.inpP[mpb + m][kb * 4]);
                ulonglong2 p01 = p[0], p23 = p[1];
                FMA2(acc[m], w0, p01.x); FMA2(acc[m], w1, p01.y);
                FMA2(acc[m], w2, p23.x); FMA2(acc[m], w3, p23.y);
            }
            wv = wn;
        }
        #pragma unroll
        for (int m = 0; m < 4; m++) {
            float lo, hi;
            upk2(acc[m], lo, hi);
            int mp = mpb + m;
            sm.g_s[q][jj][2 * mp]     = lo;
            sm.g_s[q][jj][2 * mp + 1] = hi;
        }
        __syncthreads();

        // ---- LSTM elementwise update (each thread: 1 unit x 2 rows) ----
        for (int idx = tid; idx < 64 * MB; idx += NTH) {
            int u = idx & 63, row = idx >> 6;
            float gi = sm.g_s[0][u][row];
            float gf = sm.g_s[1][u][row];
            float gg = sm.g_s[2][u][row];
            float go = sm.g_s[3][u][row];
            float cc = sm.c_s[u][row];
            cc = sigf(gf) * cc + sigf(gi) * tanhf_(gg);
            float h = sigf(go) * tanhf_(cc);
            sm.c_s[u][row] = cc;
            __stcg(&g_hbuf[(b0 + row) * H_ + rnk * 64 + u], h);
        }
        __threadfence();
        cluster_sync_();   // full h for this group visible

        // ---- MLP head for this rank's 4 rows: 512 -> 64 -> 16 -> 2 ----
        {
            int rbase = b0 + rnk * 4;
            for (int idx = tid; idx < 4 * H_; idx += NTH) {
                int rr = idx >> 9, k = idx & 511;
                sm.hm_s[rr][k] = __ldcg(&g_hbuf[(rbase + rr) * H_ + k]);
            }
            __syncthreads();
            if (tid < 256) {
                int o = tid & 63, rr = tid >> 6;
                const float* hr = sm.hm_s[rr];
                float a0 = 0.f, a1 = 0.f, a2 = 0.f, a3 = 0.f;
                #pragma unroll 8
                for (int k = 0; k < H_; k += 4) {
                    a0 += g_W1t[k][o]     * hr[k];
                    a1 += g_W1t[k + 1][o] * hr[k + 1];
                    a2 += g_W1t[k + 2][o] * hr[k + 2];
                    a3 += g_W1t[k + 3][o] * hr[k + 3];
                }
                sm.y1[rr][o] = fmaxf(a0 + a1 + a2 + a3 + b1v, 0.f);
            }
            __syncthreads();
            if (tid < 64) {
                int o = tid & 15, rr = tid >> 4;
                float a = b2v;
                #pragma unroll
                for (int kk = 0; kk < 64; kk++) a += g_W2t[kk][o] * sm.y1[rr][kk];
                sm.y2[rr][o] = fmaxf(a, 0.f);
            }
            __syncthreads();
            if (tid < 8) {
                int o = tid & 1, rr = tid >> 1;
                float a = __ldg(&b3[o]);
                #pragma unroll
                for (int kk = 0; kk < 16; kk++)
                    a += __ldg(&W3[o * 16 + kk]) * sm.y2[rr][kk];
                a = fmaxf(a, 0.f);
                int b = rbase + rr;
                out[(b * L_ + t) * 2 + o] = a;       // predicted_pos[b, t, o]
                __stcg(&g_ybuf[b * 2 + o], a);       // feedback
            }
        }
        __threadfence();
        cluster_sync_();   // y ready for next step's fill
    }

    // ---- final h, c outputs ----
    for (int idx = tid; idx < 64 * MB; idx += NTH) {
        int u = idx & 63, row = idx >> 6;
        int b = b0 + row, ug = rnk * 64 + u;
        out[B_ * L_ * 2 + b * H_ + ug]            = __ldcg(&g_hbuf[b * H_ + ug]);
        out[B_ * L_ * 2 + B_ * H_ + b * H_ + ug]  = sm.c_s[u][row];
    }
}

// ---------------------------------------------------------------------------
extern "C" void kernel_launch(void* const* d_in, const int* in_sizes, int n_in,
                              void* d_out, int out_size) {
    const float* x    = (const float*)d_in[0];
    const float* pos  = (const float*)d_in[1];
    const float* h0   = (const float*)d_in[2];
    const float* c0   = (const float*)d_in[3];
    const float* W_ih = (const float*)d_in[4];
    const float* W_hh = (const float*)d_in[5];
    const float* b_ih = (const float*)d_in[6];
    const float* b_hh = (const float*)d_in[7];
    const float* W1   = (const float*)d_in[8];
    const float* b1   = (const float*)d_in[9];
    const float* W2   = (const float*)d_in[10];
    const float* b2   = (const float*)d_in[11];
    const float* W3   = (const float*)d_in[12];
    const float* b3   = (const float*)d_in[13];
    float* out = (float*)d_out;

    pack_kernel<<<256, 256>>>(W_ih, W_hh, b_ih, b_hh, W1, W2);

    cudaFuncSetAttribute(lstm_kernel,
                         cudaFuncAttributeMaxDynamicSharedMemorySize,
                         (int)sizeof(SM));
    lstm_kernel<<<NCTAS, NTH, sizeof(SM)>>>(x, pos, h0, c0,
                                            b1, b2, W3, b3, out);
}